// round 8
// baseline (speedup 1.0000x reference)
#include <cuda_runtime.h>
#include <cstdint>
#include <cstddef>

#define NQ   25200
#define NB   16
#define NCLS 80
#define PC   85
#define TOPK 1024
#define MAXDET 300
#define CONF_THF 0.6f
#define IOU_THF  0.45f
#define MAX_WHF  4096.0f
#define CAND_CAP 2048
#define FULLM 0xffffffffu

// ---------------- scratch ----------------
__device__ float g_score[NB * NQ];
__device__ int   g_cls[NB * NQ];

__device__ __forceinline__ unsigned f2ord(float f) {
    unsigned u = __float_as_uint(f);
    return (u & 0x80000000u) ? ~u : (u | 0x80000000u);
}

// ---------------- kernel 1: smem-staged, thread-per-anchor score/argmax ----------------
#define K1_ANCH 256
#define K1_SMEM (K1_ANCH * PC * 4)          // 87040 B
#define K1_VEC  (K1_ANCH * PC / 4)          // 5440 float4 per CTA

__global__ void __launch_bounds__(256) k1_score(const float* __restrict__ pred) {
    extern __shared__ float s_row[];
    int tid = threadIdx.x;
    size_t blk_base_v = (size_t)blockIdx.x * K1_VEC;
    const float4* gp4 = (const float4*)pred;
    float4* sp4 = (float4*)s_row;
    #pragma unroll
    for (int v = tid; v < K1_VEC; v += 256) sp4[v] = __ldg(gp4 + blk_base_v + v);
    __syncthreads();

    const float* row = s_row + tid * PC;
    float obj = row[4];
    float best = -1e30f;
    int bidx = 0;
    #pragma unroll 8
    for (int c = 0; c < NCLS; ++c) {
        float p = __fmul_rn(row[5 + c], obj);
        if (p > best) { best = p; bidx = c; }   // strict > keeps lowest c (jnp.argmax)
    }
    int a = blockIdx.x * K1_ANCH + tid;
    bool valid = (obj > CONF_THF) && (best > CONF_THF);
    g_score[a] = valid ? best : -1.0f;
    g_cls[a]   = bidx;
}

// ---------------- fused kernel 2: select + sort + IoU mask + resolve + output ----------------
// dynamic smem layout (bytes):
//   [0, 135168)         region M: phase A = s_ord[NQ] (100800 B); phase B = mask[1024*33] (135168 B)
//   [135168+16384? ...]  see offsets below
#define OFF_KEY   135168
#define OFF_OBOX  (OFF_KEY + CAND_CAP * 8)        // 151552: ox1,oy1,ox2,oy2,area (5*4096)
#define OFF_RAW   (OFF_OBOX + 5 * TOPK * 4)       // 172032: x1,y1,x2,y2 (4*4096)
#define OFF_SCR   (OFF_RAW + 4 * TOPK * 4)        // 188416
#define OFF_CLS   (OFF_SCR + TOPK * 4)            // 192512
#define OFF_AIDX  (OFF_CLS + TOPK * 4)            // 196608
#define K2_SMEM   (OFF_AIDX + TOPK * 4)           // 200704

__device__ __forceinline__ void wstage(unsigned long long& v, int lane, unsigned idx,
                                       unsigned kk2, unsigned jj) {
    unsigned long long o = __shfl_xor_sync(FULLM, v, jj);
    bool low = ((lane & jj) == 0);
    bool up  = ((idx & kk2) == 0);
    unsigned long long mn = (v < o) ? v : o;
    unsigned long long mx = (v < o) ? o : v;
    v = (low == up) ? mn : mx;
}

__global__ void __launch_bounds__(1024) k2_fused(const float* __restrict__ pred,
                                                 const float* __restrict__ logits,
                                                 float* __restrict__ out) {
    extern __shared__ unsigned char smem[];
    unsigned* s_ord = (unsigned*)smem;                       // phase A
    unsigned* s_mask = (unsigned*)smem;                      // phase B: [i*33 + w]
    unsigned long long* s_key = (unsigned long long*)(smem + OFF_KEY);
    float* s_ox1 = (float*)(smem + OFF_OBOX);
    float* s_oy1 = s_ox1 + TOPK;
    float* s_ox2 = s_oy1 + TOPK;
    float* s_oy2 = s_ox2 + TOPK;
    float* s_oar = s_oy2 + TOPK;
    float* s_raw = (float*)(smem + OFF_RAW);                 // [4][TOPK]
    float* s_scr = (float*)(smem + OFF_SCR);
    int*   s_cls = (int*)(smem + OFF_CLS);
    int*   s_aidx = (int*)(smem + OFF_AIDX);

    __shared__ unsigned s_hist[256];
    __shared__ unsigned s_sel, s_kk;
    __shared__ int s_cnt;
    __shared__ unsigned s_validw[32];
    __shared__ int s_keep[MAXDET];
    __shared__ int s_nk;

    int img = blockIdx.x;
    int tid = threadIdx.x;
    int lane = tid & 31;
    const float* sc = g_score + img * NQ;

    // ---- phase A: load order-mapped scores ----
    for (int i = tid; i < NQ; i += 1024) s_ord[i] = f2ord(sc[i]);
    __syncthreads();

    // ---- radix select: exact key of 1024th-largest ----
    unsigned prefix = 0;
    int k = TOPK;
    for (int p = 0; p < 4; ++p) {
        int shift = 24 - 8 * p;
        unsigned fmask = (p == 0) ? 0u : (0xFFFFFFFFu << (32 - 8 * p));
        if (tid < 256) s_hist[tid] = 0;
        __syncthreads();
        #pragma unroll
        for (int r = 0; r < 25; ++r) {
            int i = tid + (r << 10);
            bool act = i < NQ;
            unsigned o = act ? s_ord[i] : 0u;
            bool in = act && (((o ^ prefix) & fmask) == 0);
            unsigned bin = (o >> shift) & 255u;
            unsigned mm = __ballot_sync(FULLM, in);
            if (in) {
                unsigned same = __match_any_sync(mm, bin);
                if ((__ffs(same) - 1) == lane)
                    atomicAdd(&s_hist[bin], __popc(same));
            }
        }
        __syncthreads();
        if (tid < 32) {
            unsigned c[8]; unsigned tot = 0;
            #pragma unroll
            for (int r = 0; r < 8; ++r) { c[r] = s_hist[tid * 8 + r]; tot += c[r]; }
            unsigned x = tot;
            #pragma unroll
            for (int off = 1; off < 32; off <<= 1) {
                unsigned y = __shfl_down_sync(FULLM, x, off);
                if (tid + off < 32) x += y;
            }
            unsigned acc = x - tot;
            #pragma unroll
            for (int r = 7; r >= 0; --r) {
                unsigned inc = acc + c[r];
                if ((int)inc >= k && (int)acc < k) { s_sel = (unsigned)(tid * 8 + r); s_kk = (unsigned)(k - (int)acc); }
                acc = inc;
            }
        }
        __syncthreads();
        prefix |= s_sel << shift;
        k = (int)s_kk;
        __syncthreads();
    }
    unsigned T = prefix;

    // ---- compact candidates >= T ----
    if (tid == 0) s_cnt = 0;
    __syncthreads();
    #pragma unroll
    for (int r = 0; r < 25; ++r) {
        int i = tid + (r << 10);
        bool take = (i < NQ) && (s_ord[i] >= T);
        unsigned mm = __ballot_sync(FULLM, take);
        if (mm) {
            int leader = __ffs(mm) - 1;
            int base = 0;
            if (lane == leader) base = atomicAdd(&s_cnt, __popc(mm));
            base = __shfl_sync(FULLM, base, leader);
            if (take) {
                int pos = base + __popc(mm & ((1u << lane) - 1u));
                if (pos < CAND_CAP)
                    s_key[pos] = ((unsigned long long)(~s_ord[i]) << 32) | (unsigned)i;
            }
        }
    }
    __syncthreads();
    int n = s_cnt; if (n > CAND_CAP) n = CAND_CAP;
    for (int i = n + tid; i < CAND_CAP; i += 1024) s_key[i] = ~0ull;
    __syncthreads();

    // ---- hybrid bitonic sort (score desc, idx asc) ----
    {
        int W = tid >> 5;
        unsigned ia = W * 64 + lane;
        unsigned ib = W * 64 + 32 + lane;
        {
            unsigned long long a = s_key[ia], b = s_key[ib];
            #pragma unroll
            for (unsigned kk2 = 2; kk2 <= 32; kk2 <<= 1)
                #pragma unroll
                for (unsigned jj = kk2 >> 1; jj >= 1; jj >>= 1) {
                    wstage(a, lane, ia, kk2, jj);
                    wstage(b, lane, ib, kk2, jj);
                }
            s_key[ia] = a; s_key[ib] = b;
        }
        __syncthreads();
        for (unsigned kk2 = 64; kk2 <= CAND_CAP; kk2 <<= 1) {
            for (unsigned jj = kk2 >> 1; jj >= 32; jj >>= 1) {
                unsigned t = (unsigned)tid;
                unsigned e = ((t & ~(jj - 1)) << 1) | (t & (jj - 1));
                unsigned pi = e | jj;
                bool up = ((e & kk2) == 0);
                unsigned long long a = s_key[e], b2 = s_key[pi];
                bool sw = up ? (a > b2) : (a < b2);
                if (sw) { s_key[e] = b2; s_key[pi] = a; }
                __syncthreads();
            }
            unsigned long long a = s_key[ia], b = s_key[ib];
            #pragma unroll
            for (unsigned jj = 16; jj >= 1; jj >>= 1) {
                wstage(a, lane, ia, kk2, jj);
                wstage(b, lane, ib, kk2, jj);
            }
            s_key[ia] = a; s_key[ib] = b;
            __syncthreads();
        }
    }

    // ---- gather top-1024 boxes into smem ----
    {
        unsigned long long key = s_key[tid];
        int aidx; float scr; int cls;
        if ((key >> 32) == 0xFFFFFFFFull) {
            aidx = 0; scr = -1.0f; cls = 0;
        } else {
            aidx = (int)(unsigned)(key & 0xFFFFFFFFull);
            scr  = sc[aidx];
            cls  = g_cls[img * NQ + aidx];
        }
        const float* row = pred + ((size_t)(img * NQ + aidx)) * PC;
        float cx = row[0], cy = row[1], w = row[2], h = row[3];
        float hw = __fmul_rn(w, 0.5f), hh = __fmul_rn(h, 0.5f);
        float x1 = __fsub_rn(cx, hw), y1 = __fsub_rn(cy, hh);
        float x2 = __fadd_rn(cx, hw), y2 = __fadd_rn(cy, hh);
        float off = __fmul_rn((float)cls, MAX_WHF);
        float ox1 = __fadd_rn(x1, off), oy1 = __fadd_rn(y1, off);
        float ox2 = __fadd_rn(x2, off), oy2 = __fadd_rn(y2, off);

        s_aidx[tid] = aidx;
        s_scr[tid]  = scr;
        s_cls[tid]  = cls;
        s_raw[0 * TOPK + tid] = x1; s_raw[1 * TOPK + tid] = y1;
        s_raw[2 * TOPK + tid] = x2; s_raw[3 * TOPK + tid] = y2;
        s_ox1[tid] = ox1; s_oy1[tid] = oy1; s_ox2[tid] = ox2; s_oy2[tid] = oy2;
        s_oar[tid] = __fmul_rn(__fsub_rn(ox2, ox1), __fsub_rn(oy2, oy1));

        bool v = scr > CONF_THF;
        unsigned bal = __ballot_sync(FULLM, v);
        if (lane == 0) s_validw[tid >> 5] = bal;
    }
    __syncthreads();   // boxes ready; s_ord/s_key dead -> mask region reusable

    // ---- IoU mask build: thread t = row t, stride-33 row-major (conflict-free) ----
    {
        int i = tid;
        float ax1 = s_ox1[i], ay1 = s_oy1[i], ax2 = s_ox2[i], ay2 = s_oy2[i], aar = s_oar[i];
        int w0 = i >> 5;
        unsigned* mrow = s_mask + i * 33;
        for (int w = 0; w < w0; ++w) mrow[w] = 0;
        for (int w = w0; w < 32; ++w) {
            unsigned bits = 0;
            #pragma unroll 4
            for (int b = 0; b < 32; ++b) {
                int j = w * 32 + b;
                if (j > i) {
                    float xx1 = fmaxf(ax1, s_ox1[j]);
                    float yy1 = fmaxf(ay1, s_oy1[j]);
                    float xx2 = fminf(ax2, s_ox2[j]);
                    float yy2 = fminf(ay2, s_oy2[j]);
                    float iw = fmaxf(__fsub_rn(xx2, xx1), 0.0f);
                    float ih = fmaxf(__fsub_rn(yy2, yy1), 0.0f);
                    float inter = __fmul_rn(iw, ih);
                    if (inter > 0.0f) {
                        float denom = __fadd_rn(__fsub_rn(__fadd_rn(aar, s_oar[j]), inter), 1e-9f);
                        if (__fdiv_rn(inter, denom) > IOU_THF) bits |= 1u << b;
                    }
                }
            }
            mrow[w] = bits;
        }
    }
    __syncthreads();

    // ---- word-parallel greedy resolve (single warp) ----
    if (tid < 32) {
        unsigned remv = 0;   // lane l holds suppression word l
        int nk = 0;
        unsigned above = (lane < 31) ? ~((2u << lane) - 1u) : 0u;
        for (int w = 0; w < 32 && nk < MAXDET; ++w) {
            unsigned cur = s_validw[w] & ~__shfl_sync(FULLM, remv, w);
            unsigned kept = 0;
            if (cur) {
                unsigned diag = s_mask[(w * 32 + lane) * 33 + w];
                unsigned alive = cur;
                while (alive) {
                    bool supp = ((alive >> lane) & 1u) && ((diag & alive & above) != 0u);
                    unsigned sball = __ballot_sync(FULLM, supp);
                    if (!sball) { kept |= alive; break; }
                    int b = __ffs(sball) - 1;
                    unsigned ble = (b < 31) ? ((2u << b) - 1u) : 0xFFFFFFFFu;
                    unsigned batch = alive & ble;
                    kept |= batch;
                    alive &= ~batch;
                    alive &= ~__shfl_sync(FULLM, diag, b);
                }
                int cnt = __popc(kept);
                int room = MAXDET - nk;
                while (cnt > room) { kept &= ~(1u << (31 - __clz(kept))); --cnt; }
                if ((kept >> lane) & 1u)
                    s_keep[nk + __popc(kept & ((1u << lane) - 1u))] = w * 32 + lane;
                nk += cnt;
                if (kept) {
                    const unsigned* base = s_mask + (w * 32) * 33 + lane;
                    unsigned o0 = 0, o1 = 0, o2 = 0, o3 = 0;
                    #pragma unroll
                    for (int b = 0; b < 8; ++b) {
                        if (kept & (1u << (b * 4 + 0))) o0 |= base[(b * 4 + 0) * 33];
                        if (kept & (1u << (b * 4 + 1))) o1 |= base[(b * 4 + 1) * 33];
                        if (kept & (1u << (b * 4 + 2))) o2 |= base[(b * 4 + 2) * 33];
                        if (kept & (1u << (b * 4 + 3))) o3 |= base[(b * 4 + 3) * 33];
                    }
                    remv |= (o0 | o1) | (o2 | o3);
                }
            }
        }
        if (tid == 0) s_nk = nk;
    }
    __syncthreads();
    int nk = s_nk;

    // ---- outputs ----
    float* det = out;                                  // (16,300,6)
    float* val = out + NB * MAXDET * 6;                // (16,300)
    float* lg  = out + NB * MAXDET * 6 + NB * MAXDET;  // (16,300,80)

    for (int t = tid; t < MAXDET * 6; t += 1024) {
        int s = t / 6, c = t % 6;
        float vv = 0.0f;
        if (s < nk) {
            int i = s_keep[s];
            if (c < 4)       vv = s_raw[c * TOPK + i];
            else if (c == 4) vv = s_scr[i];
            else             vv = (float)s_cls[i];
        }
        det[(img * MAXDET + s) * 6 + c] = vv;
    }
    for (int s = tid; s < MAXDET; s += 1024)
        val[img * MAXDET + s] = (s < nk) ? 1.0f : 0.0f;
    for (int t = tid; t < MAXDET * NCLS; t += 1024) {
        int s = t / NCLS, c = t % NCLS;
        float vv = 0.0f;
        if (s < nk) {
            int aidx = s_aidx[s_keep[s]];
            vv = logits[((size_t)(img * NQ + aidx)) * NCLS + c];
        }
        lg[(img * MAXDET + s) * NCLS + c] = vv;
    }
}

// ---------------- launch ----------------
extern "C" void kernel_launch(void* const* d_in, const int* in_sizes, int n_in,
                              void* d_out, int out_size) {
    const float* pred   = (const float*)d_in[0];
    const float* logits = (const float*)d_in[1];
    float* out = (float*)d_out;

    static bool attr_done = false;
    if (!attr_done) {
        cudaFuncSetAttribute(k1_score, cudaFuncAttributeMaxDynamicSharedMemorySize, K1_SMEM);
        cudaFuncSetAttribute(k2_fused, cudaFuncAttributeMaxDynamicSharedMemorySize, K2_SMEM);
        attr_done = true;
    }

    k1_score<<<NB * NQ / K1_ANCH, 256, K1_SMEM>>>(pred);
    k2_fused<<<NB, 1024, K2_SMEM>>>(pred, logits, out);
}

// round 10
// speedup vs baseline: 1.6247x; 1.6247x over previous
#include <cuda_runtime.h>
#include <cstdint>
#include <cstddef>

#define NQ   25200
#define NB   16
#define NCLS 80
#define PC   85
#define TOPK 1024
#define MAXDET 300
#define CONF_THF 0.6f
#define IOU_THF  0.45f
#define MAX_WHF  4096.0f
#define CAND_CAP 2048
#define LISTCAP  16384
#define FULLM 0xffffffffu

// ---------------- scratch (device globals: no allocation allowed) ----------------
__device__ int      g_cls[NB * NQ];
__device__ unsigned long long g_list[NB * LISTCAP];  // (ord<<32)|idx for valid anchors
__device__ int      g_cnt[NB];
__device__ int      g_selidx[NB * TOPK];
__device__ float    g_selscore[NB * TOPK];
__device__ int      g_selcls[NB * TOPK];
__device__ float    g_obox[NB * TOPK * 4];
__device__ float    g_area[NB * TOPK];
__device__ float    g_rawbox[NB * TOPK * 4];
__device__ unsigned g_mask[NB * TOPK * 32];

// ---------------- kernel 1: smem-staged score/argmax + valid-list append ----------------
#define K1B 99                               // blocks per image (99*256 >= 25200)
#define K1_SMEM (256 * PC * 4)               // 87040 B
__global__ void __launch_bounds__(256) k1_score(const float* __restrict__ pred) {
    extern __shared__ float s_row[];
    int tid = threadIdx.x;
    int lane = tid & 31;
    int img = blockIdx.y;
    int base = blockIdx.x * 256;
    int nA = NQ - base; if (nA > 256) nA = 256;
    int nVec = nA * PC / 4;                  // 5440 or 2380 (both exact)
    const float4* gp4 = (const float4*)(pred + ((size_t)img * NQ + base) * PC);
    float4* sp4 = (float4*)s_row;
    for (int v = tid; v < nVec; v += 256) sp4[v] = __ldg(gp4 + v);
    __syncthreads();

    bool valid = false;
    unsigned ord = 0;
    if (tid < nA) {
        const float* row = s_row + tid * PC;
        float obj = row[4];
        float best = -1e30f;
        int bidx = 0;
        #pragma unroll 8
        for (int c = 0; c < NCLS; ++c) {
            float p = __fmul_rn(row[5 + c], obj);
            if (p > best) { best = p; bidx = c; }   // strict > keeps lowest c (jnp.argmax)
        }
        valid = (obj > CONF_THF) && (best > CONF_THF);
        ord = __float_as_uint(best) | 0x80000000u;   // f2ord of positive float
        g_cls[img * NQ + base + tid] = bidx;
    }
    unsigned mm = __ballot_sync(FULLM, valid);       // executed by ALL threads
    if (mm) {
        int leader = __ffs(mm) - 1;
        int pos0 = 0;
        if (lane == leader) pos0 = atomicAdd(&g_cnt[img], __popc(mm));
        pos0 = __shfl_sync(FULLM, pos0, leader);
        if (valid) {
            int pos = pos0 + __popc(mm & ((1u << lane) - 1u));
            if (pos < LISTCAP)
                g_list[img * LISTCAP + pos] =
                    ((unsigned long long)ord << 32) | (unsigned)(base + tid);
        }
    }
}

// ---------------- kernel 2: list-based radix-select top-1024 + hybrid sort + gather ----------------
#define K2_SMEM (LISTCAP * 8 + CAND_CAP * 8)   // 147456 B
#define K2_ROUNDS (LISTCAP / 1024)             // 16 uniform rounds

__device__ __forceinline__ void wstage(unsigned long long& v, int lane, unsigned idx,
                                       unsigned kk2, unsigned jj) {
    unsigned long long o = __shfl_xor_sync(FULLM, v, jj);
    bool low = ((lane & jj) == 0);
    bool up  = ((idx & kk2) == 0);
    unsigned long long mn = (v < o) ? v : o;
    unsigned long long mx = (v < o) ? o : v;
    v = (low == up) ? mn : mx;
}

__global__ void __launch_bounds__(1024) k2_select(const float* __restrict__ pred) {
    extern __shared__ unsigned char k2smem[];
    unsigned long long* s_list = (unsigned long long*)k2smem;
    unsigned long long* s_key  = (unsigned long long*)(k2smem + LISTCAP * 8);

    __shared__ unsigned s_hist[256];
    __shared__ unsigned s_sel, s_kk;
    __shared__ int s_cnt;

    int img = blockIdx.x;
    int tid = threadIdx.x;
    int lane = tid & 31;

    int n = g_cnt[img];
    if (n > LISTCAP) n = LISTCAP;
    for (int i = tid; i < n; i += 1024) s_list[i] = g_list[img * LISTCAP + i];
    __syncthreads();

    unsigned T = 0;
    if (n > TOPK) {
        unsigned prefix = 0;
        int k = TOPK;
        for (int p = 0; p < 4; ++p) {
            int shift = 24 - 8 * p;
            unsigned fmask = (p == 0) ? 0u : (0xFFFFFFFFu << (32 - 8 * p));
            if (tid < 256) s_hist[tid] = 0;
            __syncthreads();
            // UNIFORM trip count: every thread runs all rounds; activity is a predicate.
            #pragma unroll
            for (int r = 0; r < K2_ROUNDS; ++r) {
                int i = tid + (r << 10);
                bool act = i < n;
                unsigned o = act ? (unsigned)(s_list[i] >> 32) : 0u;
                bool in = act && (((o ^ prefix) & fmask) == 0);
                unsigned bin = (o >> shift) & 255u;
                unsigned mm = __ballot_sync(FULLM, in);
                if (in) {
                    unsigned same = __match_any_sync(mm, bin);
                    if ((__ffs(same) - 1) == lane)
                        atomicAdd(&s_hist[bin], __popc(same));
                }
            }
            __syncthreads();
            if (tid < 32) {
                unsigned c[8]; unsigned tot = 0;
                #pragma unroll
                for (int r = 0; r < 8; ++r) { c[r] = s_hist[tid * 8 + r]; tot += c[r]; }
                unsigned x = tot;
                #pragma unroll
                for (int off = 1; off < 32; off <<= 1) {
                    unsigned y = __shfl_down_sync(FULLM, x, off);
                    if (tid + off < 32) x += y;
                }
                unsigned acc = x - tot;
                #pragma unroll
                for (int r = 7; r >= 0; --r) {
                    unsigned inc = acc + c[r];
                    if ((int)inc >= k && (int)acc < k) { s_sel = (unsigned)(tid * 8 + r); s_kk = (unsigned)(k - (int)acc); }
                    acc = inc;
                }
            }
            __syncthreads();
            prefix |= s_sel << shift;
            k = (int)s_kk;
            __syncthreads();
        }
        T = prefix;
    }

    // compact candidates with ord >= T (uniform rounds + predicate)
    if (tid == 0) s_cnt = 0;
    __syncthreads();
    #pragma unroll
    for (int r = 0; r < K2_ROUNDS; ++r) {
        int i = tid + (r << 10);
        bool act = i < n;
        unsigned o = 0, idx = 0;
        if (act) {
            unsigned long long e = s_list[i];
            o = (unsigned)(e >> 32);
            idx = (unsigned)(e & 0xFFFFFFFFull);
        }
        bool take = act && (o >= T);
        unsigned mm = __ballot_sync(FULLM, take);
        if (mm) {
            int leader = __ffs(mm) - 1;
            int base = 0;
            if (lane == leader) base = atomicAdd(&s_cnt, __popc(mm));
            base = __shfl_sync(FULLM, base, leader);
            if (take) {
                int pos = base + __popc(mm & ((1u << lane) - 1u));
                if (pos < CAND_CAP)
                    s_key[pos] = ((unsigned long long)(~o) << 32) | idx;
            }
        }
    }
    __syncthreads();
    int nc = s_cnt; if (nc > CAND_CAP) nc = CAND_CAP;
    for (int i = nc + tid; i < CAND_CAP; i += 1024) s_key[i] = ~0ull;
    __syncthreads();

    // hybrid bitonic sort ascending over (~ord, idx) -> score desc, idx asc (jax-stable)
    {
        int W = tid >> 5;
        unsigned ia = W * 64 + lane;
        unsigned ib = W * 64 + 32 + lane;
        {
            unsigned long long a = s_key[ia], b = s_key[ib];
            #pragma unroll
            for (unsigned kk2 = 2; kk2 <= 32; kk2 <<= 1)
                #pragma unroll
                for (unsigned jj = kk2 >> 1; jj >= 1; jj >>= 1) {
                    wstage(a, lane, ia, kk2, jj);
                    wstage(b, lane, ib, kk2, jj);
                }
            s_key[ia] = a; s_key[ib] = b;
        }
        __syncthreads();
        for (unsigned kk2 = 64; kk2 <= CAND_CAP; kk2 <<= 1) {
            for (unsigned jj = kk2 >> 1; jj >= 32; jj >>= 1) {
                unsigned t = (unsigned)tid;
                unsigned e = ((t & ~(jj - 1)) << 1) | (t & (jj - 1));
                unsigned pi = e | jj;
                bool up = ((e & kk2) == 0);
                unsigned long long a = s_key[e], b2 = s_key[pi];
                bool sw = up ? (a > b2) : (a < b2);
                if (sw) { s_key[e] = b2; s_key[pi] = a; }
                __syncthreads();
            }
            unsigned long long a = s_key[ia], b = s_key[ib];
            #pragma unroll
            for (unsigned jj = 16; jj >= 1; jj >>= 1) {
                wstage(a, lane, ia, kk2, jj);
                wstage(b, lane, ib, kk2, jj);
            }
            s_key[ia] = a; s_key[ib] = b;
            __syncthreads();
        }
    }

    // gather boxes for my entry
    unsigned long long key = s_key[tid];
    int aidx; float scr; int cls;
    if ((key >> 32) == 0xFFFFFFFFull) {
        aidx = 0; scr = -1.0f; cls = 0;
    } else {
        aidx = (int)(unsigned)(key & 0xFFFFFFFFull);
        unsigned ordv = ~(unsigned)(key >> 32);
        scr  = __uint_as_float(ordv & 0x7FFFFFFFu);   // exact original score
        cls  = g_cls[img * NQ + aidx];
    }
    const float* row = pred + ((size_t)(img * NQ + aidx)) * PC;
    float cx = row[0], cy = row[1], w = row[2], h = row[3];
    float hw = __fmul_rn(w, 0.5f), hh = __fmul_rn(h, 0.5f);
    float x1 = __fsub_rn(cx, hw), y1 = __fsub_rn(cy, hh);
    float x2 = __fadd_rn(cx, hw), y2 = __fadd_rn(cy, hh);
    float off = __fmul_rn((float)cls, MAX_WHF);
    float ox1 = __fadd_rn(x1, off), oy1 = __fadd_rn(y1, off);
    float ox2 = __fadd_rn(x2, off), oy2 = __fadd_rn(y2, off);

    int gi = img * TOPK + tid;
    g_selidx[gi]   = aidx;
    g_selscore[gi] = scr;
    g_selcls[gi]   = cls;
    g_rawbox[gi*4+0] = x1; g_rawbox[gi*4+1] = y1; g_rawbox[gi*4+2] = x2; g_rawbox[gi*4+3] = y2;
    g_obox[gi*4+0] = ox1; g_obox[gi*4+1] = oy1; g_obox[gi*4+2] = ox2; g_obox[gi*4+3] = oy2;
    g_area[gi] = __fmul_rn(__fsub_rn(ox2, ox1), __fsub_rn(oy2, oy1));
}

// ---------------- kernel 3: IoU bitmask, warp-per-row, lane=j, div only if inter>0 ----------------
#define K3_BLKS 32

__global__ void __launch_bounds__(256) k3_mask() {
    int img = blockIdx.y;
    __shared__ float s_x1[TOPK], s_y1[TOPK], s_x2[TOPK], s_y2[TOPK], s_ar[TOPK];
    int tid = threadIdx.x;
    int wid = tid >> 5;
    int lane = tid & 31;
    for (int j = tid; j < TOPK; j += 256) {
        float4 b = ((const float4*)g_obox)[img * TOPK + j];
        s_x1[j] = b.x; s_y1[j] = b.y; s_x2[j] = b.z; s_y2[j] = b.w;
        s_ar[j] = g_area[img * TOPK + j];
    }
    __syncthreads();

    int g = blockIdx.x * 8 + wid;
    for (int rr = 0; rr < TOPK / (K3_BLKS * 8); ++rr) {
        int i = g + rr * (K3_BLKS * 8);
        float ax1 = s_x1[i], ay1 = s_y1[i], ax2 = s_x2[i], ay2 = s_y2[i], aar = s_ar[i];
        int w0 = i >> 5;
        unsigned* mrow = g_mask + (img * TOPK + i) * 32;
        if (lane < w0) mrow[lane] = 0;
        for (int w = w0; w < 32; ++w) {
            int j = w * 32 + lane;
            float xx1 = fmaxf(ax1, s_x1[j]);
            float yy1 = fmaxf(ay1, s_y1[j]);
            float xx2 = fminf(ax2, s_x2[j]);
            float yy2 = fminf(ay2, s_y2[j]);
            float iw = fmaxf(__fsub_rn(xx2, xx1), 0.0f);
            float ih = fmaxf(__fsub_rn(yy2, yy1), 0.0f);
            float inter = __fmul_rn(iw, ih);
            bool sup = false;
            if (j > i && inter > 0.0f) {
                float denom = __fadd_rn(__fsub_rn(__fadd_rn(aar, s_ar[j]), inter), 1e-9f);
                sup = __fdiv_rn(inter, denom) > IOU_THF;
            }
            unsigned bits = __ballot_sync(FULLM, sup);
            if (lane == 0) mrow[w] = bits;
        }
    }
}

// ---------------- kernel 4: word-parallel greedy resolve + write outputs ----------------
__global__ void __launch_bounds__(1024) k4_out(const float* __restrict__ logits,
                                               float* __restrict__ out) {
    extern __shared__ unsigned s_mask[];  // TOPK*32 words = 128 KB
    __shared__ int s_keep[MAXDET];
    __shared__ unsigned s_valid[32];
    __shared__ int s_nk;
    int img = blockIdx.x;
    int tid = threadIdx.x;
    int lane = tid & 31;

    {
        const uint4* gm = (const uint4*)(g_mask + img * TOPK * 32);
        uint4* sm4 = (uint4*)s_mask;
        #pragma unroll
        for (int kk = 0; kk < 8; ++kk) {
            int t = tid + (kk << 10);
            sm4[t] = __ldg(gm + t);
        }
    }
    {
        bool v = g_selscore[img * TOPK + tid] > CONF_THF;
        unsigned bal = __ballot_sync(FULLM, v);
        if (lane == 0) s_valid[tid >> 5] = bal;
    }
    __syncthreads();

    if (tid < 32) {
        unsigned remv = 0;
        int nk = 0;
        unsigned above = (lane < 31) ? ~((2u << lane) - 1u) : 0u;
        for (int w = 0; w < 32 && nk < MAXDET; ++w) {
            unsigned cur = s_valid[w] & ~__shfl_sync(FULLM, remv, w);
            unsigned kept = 0;
            if (cur) {
                unsigned diag = s_mask[(w * 32 + lane) * 32 + w];
                unsigned alive = cur;
                while (alive) {
                    bool supp = ((alive >> lane) & 1u) && ((diag & alive & above) != 0u);
                    unsigned sball = __ballot_sync(FULLM, supp);
                    if (!sball) { kept |= alive; break; }
                    int b = __ffs(sball) - 1;
                    unsigned ble = (b < 31) ? ((2u << b) - 1u) : 0xFFFFFFFFu;
                    unsigned batch = alive & ble;
                    kept |= batch;
                    alive &= ~batch;
                    alive &= ~__shfl_sync(FULLM, diag, b);
                }
                int cnt = __popc(kept);
                int room = MAXDET - nk;
                while (cnt > room) { kept &= ~(1u << (31 - __clz(kept))); --cnt; }
                if ((kept >> lane) & 1u)
                    s_keep[nk + __popc(kept & ((1u << lane) - 1u))] = w * 32 + lane;
                nk += cnt;
                if (kept) {
                    const unsigned* base = s_mask + (w * 32) * 32 + lane;
                    unsigned o0 = 0, o1 = 0, o2 = 0, o3 = 0;
                    #pragma unroll
                    for (int b = 0; b < 8; ++b) {
                        if (kept & (1u << (b * 4 + 0))) o0 |= base[(b * 4 + 0) * 32];
                        if (kept & (1u << (b * 4 + 1))) o1 |= base[(b * 4 + 1) * 32];
                        if (kept & (1u << (b * 4 + 2))) o2 |= base[(b * 4 + 2) * 32];
                        if (kept & (1u << (b * 4 + 3))) o3 |= base[(b * 4 + 3) * 32];
                    }
                    remv |= (o0 | o1) | (o2 | o3);
                }
            }
        }
        if (tid == 0) s_nk = nk;
    }
    __syncthreads();
    int nk = s_nk;

    float* det = out;                                  // (16,300,6)
    float* val = out + NB * MAXDET * 6;                // (16,300)
    float* lg  = out + NB * MAXDET * 6 + NB * MAXDET;  // (16,300,80)

    for (int t = tid; t < MAXDET * 6; t += 1024) {
        int s = t / 6, c = t % 6;
        float vv = 0.0f;
        if (s < nk) {
            int i  = s_keep[s];
            int gi = img * TOPK + i;
            if (c < 4)       vv = g_rawbox[gi * 4 + c];
            else if (c == 4) vv = g_selscore[gi];
            else             vv = (float)g_selcls[gi];
        }
        det[(img * MAXDET + s) * 6 + c] = vv;
    }
    for (int s = tid; s < MAXDET; s += 1024)
        val[img * MAXDET + s] = (s < nk) ? 1.0f : 0.0f;
    for (int t = tid; t < MAXDET * NCLS; t += 1024) {
        int s = t / NCLS, c = t % NCLS;
        float vv = 0.0f;
        if (s < nk) {
            int i = s_keep[s];
            int aidx = g_selidx[img * TOPK + i];
            vv = logits[((size_t)(img * NQ + aidx)) * NCLS + c];
        }
        lg[(img * MAXDET + s) * NCLS + c] = vv;
    }
}

// ---------------- launch ----------------
extern "C" void kernel_launch(void* const* d_in, const int* in_sizes, int n_in,
                              void* d_out, int out_size) {
    const float* pred   = (const float*)d_in[0];
    const float* logits = (const float*)d_in[1];
    float* out = (float*)d_out;

    static void* cnt_addr = nullptr;
    static bool attr_done = false;
    if (!attr_done) {
        cudaFuncSetAttribute(k1_score, cudaFuncAttributeMaxDynamicSharedMemorySize, K1_SMEM);
        cudaFuncSetAttribute(k2_select, cudaFuncAttributeMaxDynamicSharedMemorySize, K2_SMEM);
        cudaFuncSetAttribute(k4_out, cudaFuncAttributeMaxDynamicSharedMemorySize, TOPK * 32 * 4);
        cudaGetSymbolAddress(&cnt_addr, g_cnt);
        attr_done = true;
    }

    cudaMemsetAsync(cnt_addr, 0, sizeof(int) * NB);
    k1_score<<<dim3(K1B, NB), 256, K1_SMEM>>>(pred);
    k2_select<<<NB, 1024, K2_SMEM>>>(pred);
    k3_mask<<<dim3(K3_BLKS, NB), 256>>>();
    k4_out<<<NB, 1024, TOPK * 32 * 4>>>(logits, out);
}